// round 3
// baseline (speedup 1.0000x reference)
#include <cuda_runtime.h>
#include <cuda_bf16.h>
#include <cstdint>

// Problem constants (fixed by reference)
#define VOCAB        100000
#define EMB_DIM      128
#define HIDDEN       256
#define NUM_CLASSES  20
#define B_SIZE       4096
#define S_LEN        200

typedef unsigned long long ull_t;

// Scratch for pooled vectors: 4096 * 128 floats = 2 MB (static device array; no allocs)
__device__ float g_pooled[B_SIZE * EMB_DIM];

// ---------------------------------------------------------------------------
// Helpers
// ---------------------------------------------------------------------------
__device__ __forceinline__ uint32_t smem_u32(const void* p) {
    return (uint32_t)__cvta_generic_to_shared(p);
}
__device__ __forceinline__ void cp_async16(uint32_t dst, const void* src) {
    asm volatile("cp.async.ca.shared.global [%0], [%1], 16;\n" :: "r"(dst), "l"(src));
}
__device__ __forceinline__ void cp_commit() {
    asm volatile("cp.async.commit_group;\n" ::: "memory");
}
template <int N>
__device__ __forceinline__ void cp_wait() {
    asm volatile("cp.async.wait_group %0;\n" :: "n"(N) : "memory");
}
// packed fp32x2 fma: d = a * b + d   (FFMA2, sm_10x)
#define FMA2(d, a, b) \
    asm("fma.rn.f32x2 %0, %1, %2, %0;" : "+l"(d) : "l"(a), "l"(b))

// ---------------------------------------------------------------------------
// Kernel 1: embedding gather + masked mean pooling (at its L2 roofline).
// One block (128 threads = 4 warps) per sequence.
// ---------------------------------------------------------------------------
__global__ __launch_bounds__(128) void pool_kernel(
    const int* __restrict__ x,          // [B, S] token ids (int32)
    const int* __restrict__ seq_len,    // [B]
    const float* __restrict__ emb)      // [VOCAB, 128]
{
    const int b    = blockIdx.x;
    const int tid  = threadIdx.x;
    const int warp = tid >> 5;
    const int lane = tid & 31;

    const int L = seq_len[b];
    const int* xb = x + b * S_LEN;
    const float4* __restrict__ emb4 = reinterpret_cast<const float4*>(emb);

    float4 a0 = make_float4(0.f, 0.f, 0.f, 0.f);
    float4 a1 = make_float4(0.f, 0.f, 0.f, 0.f);

    int s = warp;
    for (; s + 4 < L; s += 8) {
        int t0 = xb[s];
        int t1 = xb[s + 4];
        float4 v0 = __ldg(&emb4[(size_t)t0 * 32 + lane]);
        float4 v1 = __ldg(&emb4[(size_t)t1 * 32 + lane]);
        a0.x += v0.x; a0.y += v0.y; a0.z += v0.z; a0.w += v0.w;
        a1.x += v1.x; a1.y += v1.y; a1.z += v1.z; a1.w += v1.w;
    }
    if (s < L) {
        int t0 = xb[s];
        float4 v0 = __ldg(&emb4[(size_t)t0 * 32 + lane]);
        a0.x += v0.x; a0.y += v0.y; a0.z += v0.z; a0.w += v0.w;
    }
    a0.x += a1.x; a0.y += a1.y; a0.z += a1.z; a0.w += a1.w;

    __shared__ float4 red[4][32];
    red[warp][lane] = a0;
    __syncthreads();

    if (warp == 0) {
        float4 r0 = red[0][lane];
        float4 r1 = red[1][lane];
        float4 r2 = red[2][lane];
        float4 r3 = red[3][lane];
        float inv = 1.0f / (float)L;
        float4 out;
        out.x = (r0.x + r1.x + r2.x + r3.x) * inv;
        out.y = (r0.y + r1.y + r2.y + r3.y) * inv;
        out.z = (r0.z + r1.z + r2.z + r3.z) * inv;
        out.w = (r0.w + r1.w + r2.w + r3.w) * inv;
        reinterpret_cast<float4*>(g_pooled)[b * 32 + lane] = out;
    }
}

// ---------------------------------------------------------------------------
// Kernel 2: MLP with packed fp32x2 FMAs.
//   hidden = relu(pooled @ W1 + b1); out = hidden @ W2 + b2
// 8 rows/block, 256 threads: half = tid>>7 owns 4 rows, j2 = tid&127 owns
// hidden column pair {2j2, 2j2+1}.
//   b-operand {w[k][2j2], w[k][2j2+1]}  = one LDS.64 (conflict-free)
//   a-operand {p[r][k], p[r][k]}        = broadcast LDS from duplicated sp
// W1 staged through smem in 16-row tiles, double-buffered with cp.async.
// ---------------------------------------------------------------------------
#define MLP_ROWS 8
#define KTILE    16
#define NKTILES  (EMB_DIM / KTILE)   // 8
#define RH       (MLP_ROWS / 2)      // rows per half = 4

__global__ __launch_bounds__(256) void mlp_kernel(
    const float* __restrict__ W1,   // [128, 256] row-major
    const float* __restrict__ b1,   // [256]
    const float* __restrict__ W2,   // [256, 20]  row-major
    const float* __restrict__ b2,   // [20]
    float* __restrict__ out)        // [B, 20]
{
    __shared__ float sp_dup[MLP_ROWS][2 * EMB_DIM];   //  8 KB duplicated pooled
    __shared__ float sW[2][KTILE][HIDDEN];            // 32 KB W1 double buffer
    __shared__ float sh[MLP_ROWS][HIDDEN];            //  8 KB hidden tile

    const int tid  = threadIdx.x;
    const int half = tid >> 7;      // 0/1 : which 4 rows
    const int j2   = tid & 127;     // column pair {2j2, 2j2+1}
    const int rb   = blockIdx.x * MLP_ROWS;

    // ---- stage pooled rows, duplicating each element (p -> {p,p}) ----
    {
        // 8 rows * 128 = 256 float4 loads; thread tid handles float4 #tid
        const float4 p4 = reinterpret_cast<const float4*>(g_pooled + rb * EMB_DIM)[tid];
        const int r  = tid >> 5;          // row 0..7
        const int kb = (tid & 31) * 4;    // k base 0..124
        float4 d0 = make_float4(p4.x, p4.x, p4.y, p4.y);
        float4 d1 = make_float4(p4.z, p4.z, p4.w, p4.w);
        float4* dst = reinterpret_cast<float4*>(&sp_dup[r][2 * kb]);
        dst[0] = d0;
        dst[1] = d1;
    }

    // ---- prologue: async-load W1 tile 0 (16 KB = 4 chunks/thread) ----
    {
        const char* src = (const char*)W1;
        uint32_t dst = smem_u32(&sW[0][0][0]);
        #pragma unroll
        for (int i = 0; i < 4; i++)
            cp_async16(dst + (tid + i * 256) * 16, src + (tid + i * 256) * 16);
        cp_commit();
    }

    // ---- accumulators: 4 rows x 1 col-pair, init with bias pair ----
    ull_t h2[RH];
    {
        const ull_t bpair = *reinterpret_cast<const ull_t*>(b1 + 2 * j2);
        #pragma unroll
        for (int r = 0; r < RH; r++) h2[r] = bpair;
    }

    // ---- main pipeline over k-tiles ----
    #pragma unroll 1
    for (int kt = 0; kt < NKTILES; kt++) {
        if (kt + 1 < NKTILES) {
            const char* src = (const char*)W1 + (size_t)(kt + 1) * KTILE * HIDDEN * 4;
            uint32_t dst = smem_u32(&sW[(kt + 1) & 1][0][0]);
            #pragma unroll
            for (int i = 0; i < 4; i++)
                cp_async16(dst + (tid + i * 256) * 16, src + (tid + i * 256) * 16);
            cp_commit();
            cp_wait<1>();
        } else {
            cp_wait<0>();
        }
        __syncthreads();

        const float* wt = &sW[kt & 1][0][0];
        const int kg = kt * KTILE;   // global k base of this tile
        #pragma unroll
        for (int k = 0; k < KTILE; k += 2) {
            const ull_t w0 = *reinterpret_cast<const ull_t*>(&wt[(k + 0) * HIDDEN + 2 * j2]);
            const ull_t w1 = *reinterpret_cast<const ull_t*>(&wt[(k + 1) * HIDDEN + 2 * j2]);
            #pragma unroll
            for (int r = 0; r < RH; r++) {
                const ulonglong2 pq = *reinterpret_cast<const ulonglong2*>(
                    &sp_dup[half * RH + r][2 * (kg + k)]);
                FMA2(h2[r], pq.x, w0);
                FMA2(h2[r], pq.y, w1);
            }
        }
        __syncthreads();   // tile consumed before its buffer is rewritten
    }

    // ---- relu + store hidden pairs ----
    #pragma unroll
    for (int r = 0; r < RH; r++) {
        float lo = __uint_as_float((unsigned)(h2[r] & 0xffffffffull));
        float hi = __uint_as_float((unsigned)(h2[r] >> 32));
        lo = fmaxf(lo, 0.0f);
        hi = fmaxf(hi, 0.0f);
        ull_t pair = (ull_t)__float_as_uint(lo) | ((ull_t)__float_as_uint(hi) << 32);
        *reinterpret_cast<ull_t*>(&sh[half * RH + r][2 * j2]) = pair;
    }
    __syncthreads();

    // ---- output layer: 8 rows x 20 classes = 160 dots of length 256 ----
    if (tid < MLP_ROWS * NUM_CLASSES) {
        int r = tid / NUM_CLASSES;
        int c = tid % NUM_CLASSES;
        float acc = b2[c];
        #pragma unroll 4
        for (int k = 0; k < HIDDEN; k += 4) {
            acc = fmaf(sh[r][k + 0], __ldg(&W2[(k + 0) * NUM_CLASSES + c]), acc);
            acc = fmaf(sh[r][k + 1], __ldg(&W2[(k + 1) * NUM_CLASSES + c]), acc);
            acc = fmaf(sh[r][k + 2], __ldg(&W2[(k + 2) * NUM_CLASSES + c]), acc);
            acc = fmaf(sh[r][k + 3], __ldg(&W2[(k + 3) * NUM_CLASSES + c]), acc);
        }
        out[(rb + r) * NUM_CLASSES + c] = acc;
    }
}

// ---------------------------------------------------------------------------
// Inputs (metadata order): x[int32 B*S], seq_lengths[int32 B], emb[f32],
//                          W1[f32], b1[f32], W2[f32], b2[f32]
// Output: f32 [B, 20]
// ---------------------------------------------------------------------------
extern "C" void kernel_launch(void* const* d_in, const int* in_sizes, int n_in,
                              void* d_out, int out_size)
{
    const int*   x   = (const int*)  d_in[0];
    const int*   len = (const int*)  d_in[1];
    const float* emb = (const float*)d_in[2];
    const float* W1  = (const float*)d_in[3];
    const float* b1  = (const float*)d_in[4];
    const float* W2  = (const float*)d_in[5];
    const float* b2  = (const float*)d_in[6];
    float* out = (float*)d_out;

    pool_kernel<<<B_SIZE, 128>>>(x, len, emb);
    mlp_kernel<<<B_SIZE / MLP_ROWS, 256>>>(W1, b1, W2, b2, out);
}

// round 4
// speedup vs baseline: 1.0471x; 1.0471x over previous
#include <cuda_runtime.h>
#include <cuda_bf16.h>
#include <cstdint>

// Problem constants (fixed by reference)
#define VOCAB        100000
#define EMB_DIM      128
#define HIDDEN       256
#define NUM_CLASSES  20
#define B_SIZE       4096
#define S_LEN        200

typedef unsigned long long ull_t;

// Scratch for pooled vectors: 4096 * 128 floats = 2 MB (static device array; no allocs)
__device__ float g_pooled[B_SIZE * EMB_DIM];

// ---------------------------------------------------------------------------
// Helpers
// ---------------------------------------------------------------------------
__device__ __forceinline__ uint32_t smem_u32(const void* p) {
    return (uint32_t)__cvta_generic_to_shared(p);
}
// 1D bulk async copy gmem -> smem (TMA path, one instruction, no per-thread LDGSTS)
__device__ __forceinline__ void bulk_g2s(uint32_t dst, const void* src,
                                         uint32_t bytes, uint32_t mbar) {
    asm volatile(
        "cp.async.bulk.shared::cta.global.mbarrier::complete_tx::bytes [%0], [%1], %2, [%3];"
        :: "r"(dst), "l"(src), "r"(bytes), "r"(mbar) : "memory");
}
__device__ __forceinline__ void mbar_init(uint32_t mbar, uint32_t cnt) {
    asm volatile("mbarrier.init.shared.b64 [%0], %1;" :: "r"(mbar), "r"(cnt) : "memory");
}
__device__ __forceinline__ void mbar_expect_tx(uint32_t mbar, uint32_t bytes) {
    asm volatile("mbarrier.arrive.expect_tx.shared.b64 _, [%0], %1;"
                 :: "r"(mbar), "r"(bytes) : "memory");
}
__device__ __forceinline__ void mbar_wait(uint32_t mbar, uint32_t parity) {
    asm volatile(
        "{\n\t"
        ".reg .pred P1;\n\t"
        "WAIT_LOOP_%=:\n\t"
        "mbarrier.try_wait.parity.acquire.cta.shared::cta.b64 P1, [%0], %1, 0x989680;\n\t"
        "@P1 bra.uni WAIT_DONE_%=;\n\t"
        "bra.uni WAIT_LOOP_%=;\n\t"
        "WAIT_DONE_%=:\n\t"
        "}"
        :: "r"(mbar), "r"(parity) : "memory");
}
// packed fp32x2 fma: d = a * b + d
#define FMA2(d, a, b) \
    asm("fma.rn.f32x2 %0, %1, %2, %0;" : "+l"(d) : "l"(a), "l"(b))

__device__ __forceinline__ ull_t pack2(float lo, float hi) {
    ull_t v;
    asm("mov.b64 %0, {%1, %2};" : "=l"(v) : "f"(lo), "f"(hi));
    return v;
}
__device__ __forceinline__ void unpack2(ull_t v, float& lo, float& hi) {
    asm("mov.b64 {%0, %1}, %2;" : "=f"(lo), "=f"(hi) : "l"(v));
}

// ---------------------------------------------------------------------------
// Kernel 1: embedding gather + masked mean pooling (at its L2-gather roofline).
// One block (128 threads = 4 warps) per sequence.
// ---------------------------------------------------------------------------
__global__ __launch_bounds__(128) void pool_kernel(
    const int* __restrict__ x,          // [B, S] token ids (int32)
    const int* __restrict__ seq_len,    // [B]
    const float* __restrict__ emb)      // [VOCAB, 128]
{
    const int b    = blockIdx.x;
    const int tid  = threadIdx.x;
    const int warp = tid >> 5;
    const int lane = tid & 31;

    const int L = seq_len[b];
    const int* xb = x + b * S_LEN;
    const float4* __restrict__ emb4 = reinterpret_cast<const float4*>(emb);

    float4 a0 = make_float4(0.f, 0.f, 0.f, 0.f);
    float4 a1 = make_float4(0.f, 0.f, 0.f, 0.f);

    int s = warp;
    for (; s + 4 < L; s += 8) {
        int t0 = xb[s];
        int t1 = xb[s + 4];
        float4 v0 = __ldg(&emb4[(size_t)t0 * 32 + lane]);
        float4 v1 = __ldg(&emb4[(size_t)t1 * 32 + lane]);
        a0.x += v0.x; a0.y += v0.y; a0.z += v0.z; a0.w += v0.w;
        a1.x += v1.x; a1.y += v1.y; a1.z += v1.z; a1.w += v1.w;
    }
    if (s < L) {
        int t0 = xb[s];
        float4 v0 = __ldg(&emb4[(size_t)t0 * 32 + lane]);
        a0.x += v0.x; a0.y += v0.y; a0.z += v0.z; a0.w += v0.w;
    }
    a0.x += a1.x; a0.y += a1.y; a0.z += a1.z; a0.w += a1.w;

    __shared__ float4 red[4][32];
    red[warp][lane] = a0;
    __syncthreads();

    if (warp == 0) {
        float4 r0 = red[0][lane];
        float4 r1 = red[1][lane];
        float4 r2 = red[2][lane];
        float4 r3 = red[3][lane];
        float inv = 1.0f / (float)L;
        float4 out;
        out.x = (r0.x + r1.x + r2.x + r3.x) * inv;
        out.y = (r0.y + r1.y + r2.y + r3.y) * inv;
        out.z = (r0.z + r1.z + r2.z + r3.z) * inv;
        out.w = (r0.w + r1.w + r2.w + r3.w) * inv;
        reinterpret_cast<float4*>(g_pooled)[b * 32 + lane] = out;
    }
}

// ---------------------------------------------------------------------------
// Kernel 2: MLP, persistent-W1 + register-blocked.
//   grid = 128 blocks x 256 threads, 32 rows per block, 1 block/SM.
//   W1 (128 KB) loaded ONCE per block via cp.async.bulk into smem.
//   Thread (g = tid>>6, c = tid&63): rows [8g,8g+8), cols [4c,4c+4).
//   16 ull accumulators (8 rows x 2 col-pairs), fp32x2 FMAs.
//   Inner loop per 2 k: 2 weight LDS.128 + 8 broadcast LDS.128 + 32 FFMA2.
// ---------------------------------------------------------------------------
#define MLP_ROWS   32
#define MLP_GRID   (B_SIZE / MLP_ROWS)    // 128
#define SW_FLOATS  (EMB_DIM * HIDDEN)     // 32768 (128 KB)
#define SP_FLOATS  (MLP_ROWS * 2 * EMB_DIM) // 8192 (32 KB, duplicated)
#define SH_FLOATS  (MLP_ROWS * HIDDEN)    // 8192 (32 KB)
#define MLP_SMEM_BYTES ((SW_FLOATS + SP_FLOATS + SH_FLOATS) * 4)  // 192 KB

__global__ void __launch_bounds__(256, 1) mlp_kernel(
    const float* __restrict__ W1,   // [128, 256] row-major
    const float* __restrict__ b1,   // [256]
    const float* __restrict__ W2,   // [256, 20]  row-major
    const float* __restrict__ b2,   // [20]
    float* __restrict__ out)        // [B, 20]
{
    extern __shared__ float smem[];
    float* sW = smem;                       // [128][256]
    float* sp = smem + SW_FLOATS;           // [32][256] duplicated pooled
    float* sh = smem + SW_FLOATS + SP_FLOATS; // [32][256] hidden
    __shared__ ull_t mbar_store;
    const uint32_t mb = smem_u32(&mbar_store);

    const int tid = threadIdx.x;
    const int rb  = blockIdx.x * MLP_ROWS;

    if (tid == 0) mbar_init(mb, 1);
    __syncthreads();

    // ---- one-shot W1 staging: 8 x 16 KB bulk copies, single mbarrier ----
    if (tid == 0) {
        mbar_expect_tx(mb, SW_FLOATS * 4);
        uint32_t dst = smem_u32(sW);
        #pragma unroll
        for (int i = 0; i < 8; i++)
            bulk_g2s(dst + i * 16384, (const char*)W1 + i * 16384, 16384, mb);
    }

    // ---- stage pooled rows (duplicated p -> {p,p}), overlapped with TMA ----
    {
        const float4* gp = reinterpret_cast<const float4*>(g_pooled + rb * EMB_DIM);
        #pragma unroll
        for (int i = 0; i < 4; i++) {
            int idx = tid + i * 256;            // 0..1023
            float4 p = gp[idx];
            int r  = idx >> 5;                  // row 0..31
            int kb = (idx & 31) * 4;            // k base
            float4* d = reinterpret_cast<float4*>(sp + r * 2 * EMB_DIM + 2 * kb);
            d[0] = make_float4(p.x, p.x, p.y, p.y);
            d[1] = make_float4(p.z, p.z, p.w, p.w);
        }
    }
    __syncthreads();                 // sp visible to all threads
    mbar_wait(mb, 0);                // W1 resident (acquire)

    // ---- layer 1: register-blocked 8 rows x 4 cols per thread ----
    const int g = tid >> 6;          // row group 0..3 -> rows [8g, 8g+8)
    const int c = tid & 63;          // col quad -> cols [4c, 4c+4)
    const float* wcol = sW + 4 * c;
    const float* prow = sp + (g * 8) * (2 * EMB_DIM);

    ull_t acc[8][2];
    {
        float4 b4 = *reinterpret_cast<const float4*>(b1 + 4 * c);
        ull_t blo = pack2(b4.x, b4.y);
        ull_t bhi = pack2(b4.z, b4.w);
        #pragma unroll
        for (int r = 0; r < 8; r++) { acc[r][0] = blo; acc[r][1] = bhi; }
    }

    #pragma unroll 2
    for (int k = 0; k < EMB_DIM; k += 2) {
        ulonglong2 w0 = *reinterpret_cast<const ulonglong2*>(wcol + (k + 0) * HIDDEN);
        ulonglong2 w1 = *reinterpret_cast<const ulonglong2*>(wcol + (k + 1) * HIDDEN);
        #pragma unroll
        for (int r = 0; r < 8; r++) {
            ulonglong2 pq = *reinterpret_cast<const ulonglong2*>(
                prow + r * (2 * EMB_DIM) + 2 * k);   // {p(k),p(k)},{p(k+1),p(k+1)} broadcast
            FMA2(acc[r][0], pq.x, w0.x);
            FMA2(acc[r][1], pq.x, w0.y);
            FMA2(acc[r][0], pq.y, w1.x);
            FMA2(acc[r][1], pq.y, w1.y);
        }
    }

    // ---- relu -> sh ----
    #pragma unroll
    for (int r = 0; r < 8; r++) {
        float h0, h1, h2, h3;
        unpack2(acc[r][0], h0, h1);
        unpack2(acc[r][1], h2, h3);
        float4 hv = make_float4(fmaxf(h0, 0.f), fmaxf(h1, 0.f),
                                fmaxf(h2, 0.f), fmaxf(h3, 0.f));
        *reinterpret_cast<float4*>(&sh[(g * 8 + r) * HIDDEN + 4 * c]) = hv;
    }
    __syncthreads();

    // ---- layer 2: 32 rows x 20 classes = 640 dots of length 256 ----
    for (int idx = tid; idx < MLP_ROWS * NUM_CLASSES; idx += 256) {
        int r  = idx / NUM_CLASSES;
        int cc = idx % NUM_CLASSES;
        const float* hrow = sh + r * HIDDEN;
        float acc2 = b2[cc];
        #pragma unroll 8
        for (int k = 0; k < HIDDEN; k++)
            acc2 = fmaf(hrow[k], __ldg(&W2[k * NUM_CLASSES + cc]), acc2);
        out[(rb + r) * NUM_CLASSES + cc] = acc2;
    }
}

// ---------------------------------------------------------------------------
// Inputs (metadata order): x[int32 B*S], seq_lengths[int32 B], emb[f32],
//                          W1[f32], b1[f32], W2[f32], b2[f32]
// Output: f32 [B, 20]
// ---------------------------------------------------------------------------
extern "C" void kernel_launch(void* const* d_in, const int* in_sizes, int n_in,
                              void* d_out, int out_size)
{
    const int*   x   = (const int*)  d_in[0];
    const int*   len = (const int*)  d_in[1];
    const float* emb = (const float*)d_in[2];
    const float* W1  = (const float*)d_in[3];
    const float* b1  = (const float*)d_in[4];
    const float* W2  = (const float*)d_in[5];
    const float* b2  = (const float*)d_in[6];
    float* out = (float*)d_out;

    cudaFuncSetAttribute(mlp_kernel,
                         cudaFuncAttributeMaxDynamicSharedMemorySize,
                         MLP_SMEM_BYTES);

    pool_kernel<<<B_SIZE, 128>>>(x, len, emb);
    mlp_kernel<<<MLP_GRID, 256, MLP_SMEM_BYTES>>>(W1, b1, W2, b2, out);
}